// round 7
// baseline (speedup 1.0000x reference)
#include <cuda_runtime.h>
#include <stdint.h>
#include <math.h>

// Problem constants (fixed by setup_inputs)
#define Bq 2
#define Lq 4096
#define Hq 8
#define Dq 64
#define Mq 128
#define Cq 64
#define NCq (Lq / Cq)      // 64 chunks
#define BHq (Bq * Hq)      // 16 sequences

#define RATIO 0.08838834764831845f   // 1/sqrt(128)
#define STAB  1e-3f

// ---------------- scratch (device globals; no runtime allocation) ----------
__device__ float g_kv[BHq * NCq * Mq * Dq];    // [bh, c, m, d] -> exclusive prefix
__device__ float g_ks[BHq * NCq * Mq];         // [bh, c, m]   -> exclusive prefix

// ---------------- helpers ----------------
__device__ __forceinline__ float4 f4z() { return make_float4(0.f, 0.f, 0.f, 0.f); }
__device__ __forceinline__ void add4(float4& a, float4 b) {
    a.x += b.x; a.y += b.y; a.z += b.z; a.w += b.w;
}
__device__ __forceinline__ uint32_t f2tf(float x) {
    uint32_t r; asm("cvt.rna.tf32.f32 %0, %1;" : "=r"(r) : "f"(x)); return r;
}
__device__ __forceinline__ uint4 cvt4(float4 v) {
    return make_uint4(f2tf(v.x), f2tf(v.y), f2tf(v.z), f2tf(v.w));
}
// m16n8k8 tf32 mma, fp32 accumulate (D = A*B + D)
__device__ __forceinline__ void mma8(float* c, uint32_t a0, uint32_t a1, uint32_t a2, uint32_t a3,
                                     uint32_t b0, uint32_t b1) {
    asm("mma.sync.aligned.m16n8k8.row.col.f32.tf32.tf32.f32 "
        "{%0,%1,%2,%3},{%4,%5,%6,%7},{%8,%9},{%0,%1,%2,%3};"
        : "+f"(c[0]), "+f"(c[1]), "+f"(c[2]), "+f"(c[3])
        : "r"(a0), "r"(a1), "r"(a2), "r"(a3), "r"(b0), "r"(b1));
}
__device__ __forceinline__ float relu_s(float x) { return fmaxf(x * RATIO, 0.f) + STAB; }

// ======================= Kernel 1: chunk kp -> KV / ksum ====================
// grid BH*NC, 512 threads (16 warps), 2 CTAs/SM.
// smem u32: Xk [64][68] | Ps [128][68] | kpT [128][68] | vT [64][68]
#define CKV_SMEM ((4352 + 8704 + 8704 + 4352) * 4)
__global__ void __launch_bounds__(512, 2) chunkkv_kernel(
        const float* __restrict__ K, const float* __restrict__ V,
        const float* __restrict__ P) {
    extern __shared__ uint32_t sm[];
    uint32_t* Xk  = sm;                 // [64][68]
    uint32_t* Ps  = Xk + 4352;          // [128][68]
    uint32_t* kpT = Ps + 8704;          // [128][68]  (kp transposed: [m][l])
    uint32_t* vT  = kpT + 8704;         // [64][68]   ([d][l])

    int bid = blockIdx.x;
    int bh = bid / NCq, c = bid % NCq;
    int b = bh / Hq, h = bh % Hq;
    int tid = threadIdx.x;
    int lbase = c * Cq;

    for (int i = tid; i < 128 * 16; i += 512) {
        int m = i >> 4, d4 = i & 15;
        float4 v = reinterpret_cast<const float4*>(P)[m * 16 + d4];
        *reinterpret_cast<uint4*>(&Ps[m * 68 + d4 * 4]) = cvt4(v);
    }
    for (int i = tid; i < 64 * 16; i += 512) {
        int l = i >> 4, d4 = i & 15;
        float4 v = reinterpret_cast<const float4*>(K)[((b * Lq + lbase + l) * Hq + h) * 16 + d4];
        *reinterpret_cast<uint4*>(&Xk[l * 68 + d4 * 4]) = cvt4(v);
        float4 vv = reinterpret_cast<const float4*>(V)[((b * Lq + lbase + l) * Hq + h) * 16 + d4];
        vT[(d4 * 4 + 0) * 68 + l] = f2tf(vv.x);
        vT[(d4 * 4 + 1) * 68 + l] = f2tf(vv.y);
        vT[(d4 * 4 + 2) * 68 + l] = f2tf(vv.z);
        vT[(d4 * 4 + 3) * 68 + l] = f2tf(vv.w);
    }
    __syncthreads();

    int wid = tid >> 5, lane = tid & 31;
    int g = lane >> 2, t = lane & 3;

    // ---- kp = relu(Xk @ P^T), stored transposed into kpT [m][l] ----
    // 16 warps: 4 l-tiles x 4 n-quarters (32 cols each)
    {
        int mt = wid & 3, nh = wid >> 2;
        int l0 = mt * 16 + g, l1 = l0 + 8;
        int ar0 = l0 * 68, ar1 = l1 * 68;
        float acc[4][4];
#pragma unroll
        for (int j = 0; j < 4; j++) acc[j][0] = acc[j][1] = acc[j][2] = acc[j][3] = 0.f;
#pragma unroll
        for (int k0 = 0; k0 < 64; k0 += 8) {
            uint32_t a0 = Xk[ar0 + k0 + t];
            uint32_t a1 = Xk[ar1 + k0 + t];
            uint32_t a2 = Xk[ar0 + k0 + t + 4];
            uint32_t a3 = Xk[ar1 + k0 + t + 4];
#pragma unroll
            for (int j = 0; j < 4; j++) {
                int n = nh * 32 + j * 8 + g;
                mma8(acc[j], a0, a1, a2, a3, Ps[n * 68 + k0 + t], Ps[n * 68 + k0 + t + 4]);
            }
        }
#pragma unroll
        for (int j = 0; j < 4; j++) {
            int col = nh * 32 + j * 8 + 2 * t;
            kpT[col * 68 + l0]       = f2tf(relu_s(acc[j][0]));
            kpT[(col + 1) * 68 + l0] = f2tf(relu_s(acc[j][1]));
            kpT[col * 68 + l1]       = f2tf(relu_s(acc[j][2]));
            kpT[(col + 1) * 68 + l1] = f2tf(relu_s(acc[j][3]));
        }
    }
    __syncthreads();

    int cbase = (bh * NCq + c) * Mq;

    // ---- ksum[m] = sum_l kp[l][m] (tf32 bits are valid fp32) ----
    {
        int m = tid >> 2, q4 = tid & 3;
        const float* kf = reinterpret_cast<const float*>(kpT);
        float s = 0.f;
        for (int l = q4; l < 64; l += 4) s += kf[m * 68 + l];
        s += __shfl_xor_sync(0xffffffffu, s, 2);
        s += __shfl_xor_sync(0xffffffffu, s, 1);
        if (q4 == 0) g_ks[cbase + m] = s;
    }

    // ---- KV = kp^T @ v : A = kpT [m][l], B = vT [d][l], K=64 ----
    // 16 warps: 8 m-tiles x 2 n-halves (32 cols each)
    {
        int mt = wid & 7, nh = wid >> 3;
        int m0 = mt * 16 + g, m1 = m0 + 8;
        int ar0 = m0 * 68, ar1 = m1 * 68;
        float acc[4][4];
#pragma unroll
        for (int j = 0; j < 4; j++) acc[j][0] = acc[j][1] = acc[j][2] = acc[j][3] = 0.f;
#pragma unroll
        for (int k0 = 0; k0 < 64; k0 += 8) {
            uint32_t a0 = kpT[ar0 + k0 + t];
            uint32_t a1 = kpT[ar1 + k0 + t];
            uint32_t a2 = kpT[ar0 + k0 + t + 4];
            uint32_t a3 = kpT[ar1 + k0 + t + 4];
#pragma unroll
            for (int j = 0; j < 4; j++) {
                int n = nh * 32 + j * 8 + g;
                mma8(acc[j], a0, a1, a2, a3, vT[n * 68 + k0 + t], vT[n * 68 + k0 + t + 4]);
            }
        }
#pragma unroll
        for (int j = 0; j < 4; j++) {
            int d = nh * 32 + j * 8 + 2 * t;
            float2 w0 = make_float2(acc[j][0], acc[j][1]);
            float2 w1 = make_float2(acc[j][2], acc[j][3]);
            reinterpret_cast<float2*>(g_kv)[((cbase + m0) * Dq + d) >> 1] = w0;
            reinterpret_cast<float2*>(g_kv)[((cbase + m1) * Dq + d) >> 1] = w1;
        }
    }
}

// ======================= Kernel 2: exclusive prefix over chunks ==============
// grid BH*8 (8 slices per bh), 256 threads; each thread owns 1 float4; MLP=4
__global__ void scan_kernel() {
    int bh    = blockIdx.x >> 3;
    int slice = blockIdx.x & 7;
    int tid   = threadIdx.x;
    int base4 = slice * 256 + tid;          // per-(bh,c) = 2048 float4
    float4* kv4 = reinterpret_cast<float4*>(g_kv);

    float4 p = f4z();
    for (int c = 0; c < NCq; c += 4) {
        int i0 = (bh * NCq + c) * 2048 + base4;
        float4 a0 = kv4[i0];
        float4 a1 = kv4[i0 + 2048];
        float4 a2 = kv4[i0 + 4096];
        float4 a3 = kv4[i0 + 6144];
        kv4[i0]        = p; add4(p, a0);
        kv4[i0 + 2048] = p; add4(p, a1);
        kv4[i0 + 4096] = p; add4(p, a2);
        kv4[i0 + 6144] = p; add4(p, a3);
    }

    if (slice == 0 && tid < 128) {
        float pk = 0.f;
        for (int c = 0; c < NCq; c += 4) {
            int i0 = (bh * NCq + c) * Mq + tid;
            float a0 = g_ks[i0], a1 = g_ks[i0 + Mq], a2 = g_ks[i0 + 2 * Mq], a3 = g_ks[i0 + 3 * Mq];
            g_ks[i0]          = pk;
            g_ks[i0 + Mq]     = pk + a0;
            g_ks[i0 + 2 * Mq] = pk + a0 + a1;
            g_ks[i0 + 3 * Mq] = pk + a0 + a1 + a2;
            pk += a0 + a1 + a2 + a3;
        }
    }
}

// ======================= Kernel 3: fused proj + output ======================
// grid BH*NC, 512 threads (16 warps), 2 CTAs/SM (104 KB smem).
// smem u32 layout:
//   Ps [128][68] 8704   (-> kvT [64][132] 8448 after proj)
//   qp_s [64][132] 8448
//   kpv 8704: phase1-2 kp_s [64][132]; phase3+: vT [64][68] + Sf [64][68]
//   ks[128]f, den[64]f
#define OUT_SMEM ((8704 + 8448 + 8704 + 192) * 4)
__global__ void __launch_bounds__(512, 2) out_kernel(
        const float* __restrict__ Q, const float* __restrict__ K,
        const float* __restrict__ V, const float* __restrict__ P,
        float* __restrict__ OUT) {
    extern __shared__ uint32_t sm[];
    uint32_t* Ps   = sm;               // [128][68] -> kvT after proj
    uint32_t* qp_s = Ps + 8704;        // [64][132]
    uint32_t* kpv  = qp_s + 8448;      // kp_s [64][132] -> vT + Sf
    float*    ks   = reinterpret_cast<float*>(kpv + 8704);  // [128]
    float*    den  = ks + 128;                              // [64]
    uint32_t* kp_s = kpv;              // alias (phases 1-2)
    uint32_t* kvT  = Ps;               // alias [64][132] ([d][m]) (phase 2+)
    uint32_t* vT   = kpv;              // alias [64][68] (phase 3+)
    uint32_t* Sfu  = kpv + 4352;       // alias [64][68] (phase 3+)
    float*    Sff  = reinterpret_cast<float*>(Sfu);

    int bid = blockIdx.x;
    int bh = bid / NCq, c = bid % NCq;
    int b = bh / Hq, h = bh % Hq;
    int tid = threadIdx.x;
    int lbase = c * Cq;

    // ---- phase 0: fill P (+ks) ----
    for (int i = tid; i < 128 * 16; i += 512) {
        int m = i >> 4, d4 = i & 15;
        float4 v = reinterpret_cast<const float4*>(P)[m * 16 + d4];
        *reinterpret_cast<uint4*>(&Ps[m * 68 + d4 * 4]) = cvt4(v);
    }
    if (tid < 128) ks[tid] = g_ks[(bh * NCq + c) * Mq + tid];
    __syncthreads();

    int wid = tid >> 5, lane = tid & 31;
    int g = lane >> 2, t = lane & 3;

    // ---- phase 1: qp/kp = relu(X @ P^T); A-fragments direct from global ----
    // warps 0-7: qp from Q; warps 8-15: kp from K. Each: 16 rows x 64 cols.
    {
        int pw = wid & 7, which = wid >> 3;
        const float* Xg = which ? K : Q;
        uint32_t* dst = which ? kp_s : qp_s;
        int mt = pw & 3, nh = pw >> 2;
        int r0 = mt * 16 + g, r1 = r0 + 8;
        const float* row0 = Xg + ((size_t)(b * Lq + lbase + r0) * Hq + h) * 64;
        const float* row1 = row0 + 8 * Hq * 64;
        float acc[8][4];
#pragma unroll
        for (int j = 0; j < 8; j++) acc[j][0] = acc[j][1] = acc[j][2] = acc[j][3] = 0.f;
#pragma unroll
        for (int k0 = 0; k0 < 64; k0 += 8) {
            uint32_t a0 = f2tf(row0[k0 + t]);
            uint32_t a1 = f2tf(row1[k0 + t]);
            uint32_t a2 = f2tf(row0[k0 + t + 4]);
            uint32_t a3 = f2tf(row1[k0 + t + 4]);
#pragma unroll
            for (int j = 0; j < 8; j++) {
                int n = nh * 64 + j * 8 + g;
                mma8(acc[j], a0, a1, a2, a3, Ps[n * 68 + k0 + t], Ps[n * 68 + k0 + t + 4]);
            }
        }
#pragma unroll
        for (int j = 0; j < 8; j++) {
            int col = nh * 64 + j * 8 + 2 * t;
            uint2 w0 = make_uint2(f2tf(relu_s(acc[j][0])), f2tf(relu_s(acc[j][1])));
            uint2 w1 = make_uint2(f2tf(relu_s(acc[j][2])), f2tf(relu_s(acc[j][3])));
            *reinterpret_cast<uint2*>(&dst[r0 * 132 + col]) = w0;
            *reinterpret_cast<uint2*>(&dst[r1 * 132 + col]) = w1;
        }
    }
    __syncthreads();

    int mt = wid & 3, nt = wid >> 2;
    int r0 = mt * 16 + g, r1 = r0 + 8;
    int qr0 = r0 * 132, qr1 = r1 * 132;

    // ---- phase 2: kv loads -> stash kvT (Ps free); S = qp @ kp^T -> sacc ----
    float4 kvreg[4];
#pragma unroll
    for (int kk = 0; kk < 4; kk++) {
        int i = tid + kk * 512;                 // 2048 float4 = 128m x 16(d4)
        int m = i >> 4, d4 = i & 15;
        kvreg[kk] = reinterpret_cast<const float4*>(g_kv)[((bh * NCq + c) * Mq + m) * 16 + d4];
    }
#pragma unroll
    for (int kk = 0; kk < 4; kk++) {
        int i = tid + kk * 512;
        int m = i >> 4, d4 = i & 15;
        kvT[(d4 * 4 + 0) * 132 + m] = f2tf(kvreg[kk].x);
        kvT[(d4 * 4 + 1) * 132 + m] = f2tf(kvreg[kk].y);
        kvT[(d4 * 4 + 2) * 132 + m] = f2tf(kvreg[kk].z);
        kvT[(d4 * 4 + 3) * 132 + m] = f2tf(kvreg[kk].w);
    }
    float sacc[2][4];
#pragma unroll
    for (int j = 0; j < 2; j++) sacc[j][0] = sacc[j][1] = sacc[j][2] = sacc[j][3] = 0.f;
#pragma unroll
    for (int k0 = 0; k0 < 128; k0 += 8) {
        uint32_t a0 = qp_s[qr0 + k0 + t];
        uint32_t a1 = qp_s[qr1 + k0 + t];
        uint32_t a2 = qp_s[qr0 + k0 + t + 4];
        uint32_t a3 = qp_s[qr1 + k0 + t + 4];
#pragma unroll
        for (int j = 0; j < 2; j++) {
            int n = nt * 16 + j * 8 + g;
            mma8(sacc[j], a0, a1, a2, a3, kp_s[n * 132 + k0 + t], kp_s[n * 132 + k0 + t + 4]);
        }
    }
    __syncthreads();   // kp_s reads done -> region reusable

    // ---- phase 3: store masked Sf; load V -> vT ----
#pragma unroll
    for (int j = 0; j < 2; j++) {
        int cb = nt * 16 + j * 8 + 2 * t;
        uint2 w0, w1;
        w0.x = (r0 >= cb)     ? f2tf(sacc[j][0]) : 0u;
        w0.y = (r0 >= cb + 1) ? f2tf(sacc[j][1]) : 0u;
        w1.x = (r1 >= cb)     ? f2tf(sacc[j][2]) : 0u;
        w1.y = (r1 >= cb + 1) ? f2tf(sacc[j][3]) : 0u;
        *reinterpret_cast<uint2*>(&Sfu[r0 * 68 + cb]) = w0;
        *reinterpret_cast<uint2*>(&Sfu[r1 * 68 + cb]) = w1;
    }
    for (int i = tid; i < 64 * 16; i += 512) {
        int l = i >> 4, d4 = i & 15;
        float4 vv = reinterpret_cast<const float4*>(V)[((b * Lq + lbase + l) * Hq + h) * 16 + d4];
        vT[(d4 * 4 + 0) * 68 + l] = f2tf(vv.x);
        vT[(d4 * 4 + 1) * 68 + l] = f2tf(vv.y);
        vT[(d4 * 4 + 2) * 68 + l] = f2tf(vv.z);
        vT[(d4 * 4 + 3) * 68 + l] = f2tf(vv.w);
    }
    __syncthreads();

    // ---- phase 4: denominator (8 lanes per row) ----
    {
        int l = tid >> 3, q8 = tid & 7;
        const float* qpf = reinterpret_cast<const float*>(qp_s);
        float s = 0.f;
        for (int lp = q8; lp < 64; lp += 8) s += Sff[l * 68 + lp];
        for (int m = q8; m < Mq; m += 8)   s = fmaf(qpf[l * 132 + m], ks[m], s);
        s += __shfl_xor_sync(0xffffffffu, s, 4);
        s += __shfl_xor_sync(0xffffffffu, s, 2);
        s += __shfl_xor_sync(0xffffffffu, s, 1);
        if (q8 == 0) den[l] = s;
    }
    __syncthreads();

    // ---- phase 5: num = S @ v (K=64) + qp @ KV (K=128); divide; store ----
    float nacc[2][4];
#pragma unroll
    for (int j = 0; j < 2; j++) nacc[j][0] = nacc[j][1] = nacc[j][2] = nacc[j][3] = 0.f;

    int sr0 = r0 * 68, sr1 = r1 * 68;
#pragma unroll
    for (int k0 = 0; k0 < 64; k0 += 8) {
        uint32_t a0 = Sfu[sr0 + k0 + t];
        uint32_t a1 = Sfu[sr1 + k0 + t];
        uint32_t a2 = Sfu[sr0 + k0 + t + 4];
        uint32_t a3 = Sfu[sr1 + k0 + t + 4];
#pragma unroll
        for (int j = 0; j < 2; j++) {
            int n = nt * 16 + j * 8 + g;
            mma8(nacc[j], a0, a1, a2, a3, vT[n * 68 + k0 + t], vT[n * 68 + k0 + t + 4]);
        }
    }
#pragma unroll
    for (int k0 = 0; k0 < 128; k0 += 8) {
        uint32_t a0 = qp_s[qr0 + k0 + t];
        uint32_t a1 = qp_s[qr1 + k0 + t];
        uint32_t a2 = qp_s[qr0 + k0 + t + 4];
        uint32_t a3 = qp_s[qr1 + k0 + t + 4];
#pragma unroll
        for (int j = 0; j < 2; j++) {
            int n = nt * 16 + j * 8 + g;
            mma8(nacc[j], a0, a1, a2, a3, kvT[n * 132 + k0 + t], kvT[n * 132 + k0 + t + 4]);
        }
    }

    float i0 = 1.0f / den[r0];
    float i1 = 1.0f / den[r1];
    int ob = (b * Lq + lbase) * Hq + h;
#pragma unroll
    for (int j = 0; j < 2; j++) {
        int d = nt * 16 + j * 8 + 2 * t;
        float2 w0 = make_float2(nacc[j][0] * i0, nacc[j][1] * i0);
        float2 w1 = make_float2(nacc[j][2] * i1, nacc[j][3] * i1);
        reinterpret_cast<float2*>(OUT)[((ob + r0 * Hq) * Dq + d) >> 1] = w0;
        reinterpret_cast<float2*>(OUT)[((ob + r1 * Hq) * Dq + d) >> 1] = w1;
    }
}

// ============================ launch ============================
extern "C" void kernel_launch(void* const* d_in, const int* in_sizes, int n_in,
                              void* d_out, int out_size) {
    (void)in_sizes; (void)n_in; (void)out_size;
    const float* Q = (const float*)d_in[0];
    const float* K = (const float*)d_in[1];
    const float* V = (const float*)d_in[2];
    const float* P = (const float*)d_in[3];
    float* OUT = (float*)d_out;

    cudaFuncSetAttribute(chunkkv_kernel, cudaFuncAttributeMaxDynamicSharedMemorySize, CKV_SMEM);
    cudaFuncSetAttribute(out_kernel,     cudaFuncAttributeMaxDynamicSharedMemorySize, OUT_SMEM);

    chunkkv_kernel<<<BHq * NCq, 512, CKV_SMEM>>>(K, V, P);
    scan_kernel<<<BHq * 8, 256>>>();
    out_kernel<<<BHq * NCq, 512, OUT_SMEM>>>(Q, K, V, P, OUT);
}

// round 8
// speedup vs baseline: 1.2944x; 1.2944x over previous
#include <cuda_runtime.h>
#include <stdint.h>
#include <math.h>

// Problem constants (fixed by setup_inputs)
#define Bq 2
#define Lq 4096
#define Hq 8
#define Dq 64
#define Mq 128
#define Cq 64
#define NCq (Lq / Cq)      // 64 chunks
#define BHq (Bq * Hq)      // 16 sequences

#define RATIO 0.08838834764831845f   // 1/sqrt(128)
#define STAB  1e-3f

// ---------------- scratch (device globals; no runtime allocation) ----------
__device__ float g_kv[BHq * NCq * Mq * Dq];    // [bh, c, m, d] -> exclusive prefix
__device__ float g_ks[BHq * NCq * Mq];         // [bh, c, m]   -> exclusive prefix

// ---------------- helpers ----------------
__device__ __forceinline__ float4 f4z() { return make_float4(0.f, 0.f, 0.f, 0.f); }
__device__ __forceinline__ void add4(float4& a, float4 b) {
    a.x += b.x; a.y += b.y; a.z += b.z; a.w += b.w;
}
__device__ __forceinline__ uint32_t f2tf(float x) {
    uint32_t r; asm("cvt.rna.tf32.f32 %0, %1;" : "=r"(r) : "f"(x)); return r;
}
// k-dimension interleave: logical k -> physical pos so (k, k+4) are adjacent.
// pos = (k & ~7) + 2*(k&3) + ((k>>2)&1). LDS.64 at (k0 + 2t) yields (k0+t, k0+t+4).
__device__ __forceinline__ int kperm(int k) {
    return (k & ~7) + 2 * (k & 3) + ((k >> 2) & 1);
}
// m16n8k8 tf32 mma, fp32 accumulate (D = A*B + D)
__device__ __forceinline__ void mma8(float* c, uint32_t a0, uint32_t a1, uint32_t a2, uint32_t a3,
                                     uint32_t b0, uint32_t b1) {
    asm("mma.sync.aligned.m16n8k8.row.col.f32.tf32.tf32.f32 "
        "{%0,%1,%2,%3},{%4,%5,%6,%7},{%8,%9},{%0,%1,%2,%3};"
        : "+f"(c[0]), "+f"(c[1]), "+f"(c[2]), "+f"(c[3])
        : "r"(a0), "r"(a1), "r"(a2), "r"(a3), "r"(b0), "r"(b1));
}
__device__ __forceinline__ float relu_s(float x) { return fmaxf(x * RATIO, 0.f) + STAB; }
__device__ __forceinline__ uint2 ld2(const uint32_t* p) {
    return *reinterpret_cast<const uint2*>(p);
}

// ======================= Kernel 1: chunk kp -> KV / ksum ====================
// grid BH*NC, 256 threads (8 warps), 2 CTAs/SM (108 KB smem).
// smem u32 (k-permuted, strides 72 == 8 mod 32 -> conflict-free LDS.64):
//   Xk [64][72] | Ps [128][72] | kpT [128][72] ([m][l]) | vT [64][72] ([d][l])
#define CKV_SMEM ((4608 + 9216 + 9216 + 4608) * 4)
__global__ void __launch_bounds__(256, 2) chunkkv_kernel(
        const float* __restrict__ K, const float* __restrict__ V,
        const float* __restrict__ P) {
    extern __shared__ uint32_t sm[];
    uint32_t* Xk  = sm;                 // [64][72]   (k=d permuted)
    uint32_t* Ps  = Xk + 4608;          // [128][72]  (k=d permuted)
    uint32_t* kpT = Ps + 9216;          // [128][72]  (k=l permuted)
    uint32_t* vT  = kpT + 9216;         // [64][72]   (k=l permuted)

    int bid = blockIdx.x;
    int bh = bid / NCq, c = bid % NCq;
    int b = bh / Hq, h = bh % Hq;
    int tid = threadIdx.x;
    int lbase = c * Cq;

    // fills: vector LDG, scalar permuted STS (positions base, +2, +4, +6)
    for (int i = tid; i < 128 * 16; i += 256) {
        int m = i >> 4, d4 = i & 15;
        float4 v = reinterpret_cast<const float4*>(P)[m * 16 + d4];
        int p0 = m * 72 + (d4 >> 1) * 8 + (d4 & 1);
        Ps[p0] = f2tf(v.x); Ps[p0 + 2] = f2tf(v.y);
        Ps[p0 + 4] = f2tf(v.z); Ps[p0 + 6] = f2tf(v.w);
    }
    for (int i = tid; i < 64 * 16; i += 256) {
        int l = i >> 4, d4 = i & 15;
        int gidx = ((b * Lq + lbase + l) * Hq + h) * 16 + d4;
        float4 v = reinterpret_cast<const float4*>(K)[gidx];
        int p0 = l * 72 + (d4 >> 1) * 8 + (d4 & 1);
        Xk[p0] = f2tf(v.x); Xk[p0 + 2] = f2tf(v.y);
        Xk[p0 + 4] = f2tf(v.z); Xk[p0 + 6] = f2tf(v.w);
        float4 vv = reinterpret_cast<const float4*>(V)[gidx];
        int lp = kperm(l);
        vT[(d4 * 4 + 0) * 72 + lp] = f2tf(vv.x);
        vT[(d4 * 4 + 1) * 72 + lp] = f2tf(vv.y);
        vT[(d4 * 4 + 2) * 72 + lp] = f2tf(vv.z);
        vT[(d4 * 4 + 3) * 72 + lp] = f2tf(vv.w);
    }
    __syncthreads();

    int wid = tid >> 5, lane = tid & 31;
    int g = lane >> 2, t = lane & 3;

    // ---- kp = relu(Xk @ P^T) -> kpT [m][l] (8 warps: 4 l-tiles x 2 n-halves)
    {
        int mt = wid & 3, nh = wid >> 2;
        int l0 = mt * 16 + g, l1 = l0 + 8;
        int ar0 = l0 * 72, ar1 = l1 * 72;
        float acc[8][4];
#pragma unroll
        for (int j = 0; j < 8; j++) acc[j][0] = acc[j][1] = acc[j][2] = acc[j][3] = 0.f;
#pragma unroll
        for (int k0 = 0; k0 < 64; k0 += 8) {
            uint2 A0 = ld2(&Xk[ar0 + k0 + 2 * t]);
            uint2 A1 = ld2(&Xk[ar1 + k0 + 2 * t]);
#pragma unroll
            for (int j = 0; j < 8; j++) {
                int n = nh * 64 + j * 8 + g;
                uint2 Bn = ld2(&Ps[n * 72 + k0 + 2 * t]);
                mma8(acc[j], A0.x, A1.x, A0.y, A1.y, Bn.x, Bn.y);
            }
        }
        int kl0 = kperm(l0), kl1 = kperm(l1);
#pragma unroll
        for (int j = 0; j < 8; j++) {
            int col = nh * 64 + j * 8 + 2 * t;
            kpT[col * 72 + kl0]       = f2tf(relu_s(acc[j][0]));
            kpT[(col + 1) * 72 + kl0] = f2tf(relu_s(acc[j][1]));
            kpT[col * 72 + kl1]       = f2tf(relu_s(acc[j][2]));
            kpT[(col + 1) * 72 + kl1] = f2tf(relu_s(acc[j][3]));
        }
    }
    __syncthreads();

    int cbase = (bh * NCq + c) * Mq;

    // ---- ksum[m] = sum_l kp[l][m] (sum over permuted positions = same) ----
    {
        int m = tid >> 1, half = tid & 1;
        const float* kf = reinterpret_cast<const float*>(kpT);
        float s = 0.f;
        for (int l = 0; l < 32; l++) s += kf[m * 72 + half * 32 + l];
        s += __shfl_xor_sync(0xffffffffu, s, 1);
        if (half == 0) g_ks[cbase + m] = s;
    }

    // ---- KV = kp^T @ v : A = kpT [m][l], B = vT [d][l], K=64 ----
    {
        int m0 = wid * 16 + g, m1 = m0 + 8;
        int ar0 = m0 * 72, ar1 = m1 * 72;
        float acc[8][4];
#pragma unroll
        for (int j = 0; j < 8; j++) acc[j][0] = acc[j][1] = acc[j][2] = acc[j][3] = 0.f;
#pragma unroll
        for (int k0 = 0; k0 < 64; k0 += 8) {
            uint2 A0 = ld2(&kpT[ar0 + k0 + 2 * t]);
            uint2 A1 = ld2(&kpT[ar1 + k0 + 2 * t]);
#pragma unroll
            for (int j = 0; j < 8; j++) {
                int n = j * 8 + g;
                uint2 Bn = ld2(&vT[n * 72 + k0 + 2 * t]);
                mma8(acc[j], A0.x, A1.x, A0.y, A1.y, Bn.x, Bn.y);
            }
        }
#pragma unroll
        for (int j = 0; j < 8; j++) {
            int d = j * 8 + 2 * t;
            float2 w0 = make_float2(acc[j][0], acc[j][1]);
            float2 w1 = make_float2(acc[j][2], acc[j][3]);
            reinterpret_cast<float2*>(g_kv)[((cbase + m0) * Dq + d) >> 1] = w0;
            reinterpret_cast<float2*>(g_kv)[((cbase + m1) * Dq + d) >> 1] = w1;
        }
    }
}

// ======================= Kernel 2: exclusive prefix over chunks ==============
// grid BH*8 (8 slices per bh), 256 threads; each thread owns 1 float4; MLP=4
__global__ void scan_kernel() {
    int bh    = blockIdx.x >> 3;
    int slice = blockIdx.x & 7;
    int tid   = threadIdx.x;
    int base4 = slice * 256 + tid;          // per-(bh,c) = 2048 float4
    float4* kv4 = reinterpret_cast<float4*>(g_kv);

    float4 p = f4z();
    for (int c = 0; c < NCq; c += 4) {
        int i0 = (bh * NCq + c) * 2048 + base4;
        float4 a0 = kv4[i0];
        float4 a1 = kv4[i0 + 2048];
        float4 a2 = kv4[i0 + 4096];
        float4 a3 = kv4[i0 + 6144];
        kv4[i0]        = p; add4(p, a0);
        kv4[i0 + 2048] = p; add4(p, a1);
        kv4[i0 + 4096] = p; add4(p, a2);
        kv4[i0 + 6144] = p; add4(p, a3);
    }

    if (slice == 0 && tid < 128) {
        float pk = 0.f;
        for (int c = 0; c < NCq; c += 4) {
            int i0 = (bh * NCq + c) * Mq + tid;
            float a0 = g_ks[i0], a1 = g_ks[i0 + Mq], a2 = g_ks[i0 + 2 * Mq], a3 = g_ks[i0 + 3 * Mq];
            g_ks[i0]          = pk;
            g_ks[i0 + Mq]     = pk + a0;
            g_ks[i0 + 2 * Mq] = pk + a0 + a1;
            g_ks[i0 + 3 * Mq] = pk + a0 + a1 + a2;
            pk += a0 + a1 + a2 + a3;
        }
    }
}

// ======================= Kernel 3: fused proj + output ======================
// grid BH*NC, 512 threads (16 warps), 1 CTA/SM (159 KB smem).
// smem u32 (k-permuted; strides 72/136 == 8 mod 32):
//   Xq [64][72] (-> Sf alias) | Xk [64][72] | Ps [128][72] (-> kvT [64][136])
//   qp_s [64][136] | kp_s [64][136] | vT [64][72] | ks[128]f | den[64]f
#define OUT_SMEM ((4608 + 4608 + 9216 + 8704 + 8704 + 4608 + 192) * 4)
__global__ void __launch_bounds__(512, 1) out_kernel(
        const float* __restrict__ Q, const float* __restrict__ K,
        const float* __restrict__ V, const float* __restrict__ P,
        float* __restrict__ OUT) {
    extern __shared__ uint32_t sm[];
    uint32_t* Xq   = sm;               // [64][72] -> Sf after proj phase
    uint32_t* Xk   = Xq + 4608;        // [64][72]
    uint32_t* Ps   = Xk + 4608;        // [128][72] -> kvT [64][136] after proj
    uint32_t* qp_s = Ps + 9216;        // [64][136] (k=m permuted)
    uint32_t* kp_s = qp_s + 8704;      // [64][136] (k=m permuted)
    uint32_t* vT   = kp_s + 8704;      // [64][72]  (k=l permuted)
    float*    ks   = reinterpret_cast<float*>(vT + 4608);  // [128] (permuted)
    float*    den  = ks + 128;                              // [64]
    uint32_t* Sfu  = Xq;               // alias [64][72] (k=l permuted)
    uint32_t* kvT  = Ps;               // alias [64][136] ([d][m], k=m permuted)
    float*    Sff  = reinterpret_cast<float*>(Sfu);

    int bid = blockIdx.x;
    int bh = bid / NCq, c = bid % NCq;
    int b = bh / Hq, h = bh % Hq;
    int tid = threadIdx.x;
    int lbase = c * Cq;

    // ---- phase 0: fills ----
    for (int i = tid; i < 128 * 16; i += 512) {
        int m = i >> 4, d4 = i & 15;
        float4 v = reinterpret_cast<const float4*>(P)[m * 16 + d4];
        int p0 = m * 72 + (d4 >> 1) * 8 + (d4 & 1);
        Ps[p0] = f2tf(v.x); Ps[p0 + 2] = f2tf(v.y);
        Ps[p0 + 4] = f2tf(v.z); Ps[p0 + 6] = f2tf(v.w);
    }
    for (int i = tid; i < 64 * 16; i += 512) {
        int l = i >> 4, d4 = i & 15;
        int gidx = ((b * Lq + lbase + l) * Hq + h) * 16 + d4;
        int p0 = l * 72 + (d4 >> 1) * 8 + (d4 & 1);
        float4 q = reinterpret_cast<const float4*>(Q)[gidx];
        Xq[p0] = f2tf(q.x); Xq[p0 + 2] = f2tf(q.y);
        Xq[p0 + 4] = f2tf(q.z); Xq[p0 + 6] = f2tf(q.w);
        float4 k = reinterpret_cast<const float4*>(K)[gidx];
        Xk[p0] = f2tf(k.x); Xk[p0 + 2] = f2tf(k.y);
        Xk[p0 + 4] = f2tf(k.z); Xk[p0 + 6] = f2tf(k.w);
        float4 vv = reinterpret_cast<const float4*>(V)[gidx];
        int lp = kperm(l);
        vT[(d4 * 4 + 0) * 72 + lp] = f2tf(vv.x);
        vT[(d4 * 4 + 1) * 72 + lp] = f2tf(vv.y);
        vT[(d4 * 4 + 2) * 72 + lp] = f2tf(vv.z);
        vT[(d4 * 4 + 3) * 72 + lp] = f2tf(vv.w);
    }
    if (tid < 128) ks[kperm(tid)] = g_ks[(bh * NCq + c) * Mq + tid];
    __syncthreads();

    int wid = tid >> 5, lane = tid & 31;
    int g = lane >> 2, t = lane & 3;

    // ---- phase 1: qp/kp = relu(X @ P^T); warps 0-7 qp, 8-15 kp ----
    {
        int pw = wid & 7, which = wid >> 3;
        uint32_t* src = which ? Xk : Xq;
        uint32_t* dst = which ? kp_s : qp_s;
        int mt = pw & 3, nh = pw >> 2;
        int r0 = mt * 16 + g, r1 = r0 + 8;
        int ar0 = r0 * 72, ar1 = r1 * 72;
        float acc[8][4];
#pragma unroll
        for (int j = 0; j < 8; j++) acc[j][0] = acc[j][1] = acc[j][2] = acc[j][3] = 0.f;
#pragma unroll
        for (int k0 = 0; k0 < 64; k0 += 8) {
            uint2 A0 = ld2(&src[ar0 + k0 + 2 * t]);
            uint2 A1 = ld2(&src[ar1 + k0 + 2 * t]);
#pragma unroll
            for (int j = 0; j < 8; j++) {
                int n = nh * 64 + j * 8 + g;
                uint2 Bn = ld2(&Ps[n * 72 + k0 + 2 * t]);
                mma8(acc[j], A0.x, A1.x, A0.y, A1.y, Bn.x, Bn.y);
            }
        }
#pragma unroll
        for (int j = 0; j < 8; j++) {
            int col = nh * 64 + j * 8 + 2 * t;
            int kc0 = kperm(col), kc1 = kperm(col + 1);
            dst[r0 * 136 + kc0] = f2tf(relu_s(acc[j][0]));
            dst[r0 * 136 + kc1] = f2tf(relu_s(acc[j][1]));
            dst[r1 * 136 + kc0] = f2tf(relu_s(acc[j][2]));
            dst[r1 * 136 + kc1] = f2tf(relu_s(acc[j][3]));
        }
    }
    __syncthreads();

    int mt = wid & 3, nt = wid >> 2;
    int r0 = mt * 16 + g, r1 = r0 + 8;
    int qr0 = r0 * 136, qr1 = r1 * 136;

    // ---- phase 2: kv loads -> kvT (Ps free); S = qp @ kp^T -> masked Sf ----
    float4 kvreg[4];
#pragma unroll
    for (int kk = 0; kk < 4; kk++) {
        int i = tid + kk * 512;                 // 2048 float4 = 128m x 16(d4)
        int m = i >> 4, d4 = i & 15;
        kvreg[kk] = reinterpret_cast<const float4*>(g_kv)[((bh * NCq + c) * Mq + m) * 16 + d4];
    }
#pragma unroll
    for (int kk = 0; kk < 4; kk++) {
        int i = tid + kk * 512;
        int m = i >> 4, d4 = i & 15;
        int mp = kperm(m);
        kvT[(d4 * 4 + 0) * 136 + mp] = f2tf(kvreg[kk].x);
        kvT[(d4 * 4 + 1) * 136 + mp] = f2tf(kvreg[kk].y);
        kvT[(d4 * 4 + 2) * 136 + mp] = f2tf(kvreg[kk].z);
        kvT[(d4 * 4 + 3) * 136 + mp] = f2tf(kvreg[kk].w);
    }
    {
        float sacc[2][4];
#pragma unroll
        for (int j = 0; j < 2; j++) sacc[j][0] = sacc[j][1] = sacc[j][2] = sacc[j][3] = 0.f;
#pragma unroll
        for (int k0 = 0; k0 < 128; k0 += 8) {
            uint2 A0 = ld2(&qp_s[qr0 + k0 + 2 * t]);
            uint2 A1 = ld2(&qp_s[qr1 + k0 + 2 * t]);
#pragma unroll
            for (int j = 0; j < 2; j++) {
                int n = nt * 16 + j * 8 + g;
                uint2 Bn = ld2(&kp_s[n * 136 + k0 + 2 * t]);
                mma8(sacc[j], A0.x, A1.x, A0.y, A1.y, Bn.x, Bn.y);
            }
        }
        // masked store to Sf (k=l' permuted); Xq dead since phase-1 barrier
#pragma unroll
        for (int j = 0; j < 2; j++) {
            int cb = nt * 16 + j * 8 + 2 * t;
            int kc0 = kperm(cb), kc1 = kperm(cb + 1);
            Sfu[r0 * 72 + kc0] = (r0 >= cb)     ? f2tf(sacc[j][0]) : 0u;
            Sfu[r0 * 72 + kc1] = (r0 >= cb + 1) ? f2tf(sacc[j][1]) : 0u;
            Sfu[r1 * 72 + kc0] = (r1 >= cb)     ? f2tf(sacc[j][2]) : 0u;
            Sfu[r1 * 72 + kc1] = (r1 >= cb + 1) ? f2tf(sacc[j][3]) : 0u;
        }
    }
    __syncthreads();

    // ---- phase 3: denominator (8 lanes per row; permuted pos iteration) ----
    {
        int l = tid >> 3, q8 = tid & 7;
        int pq = 2 * (q8 & 3) + ((q8 >> 2) & 1);
        const float* qpf = reinterpret_cast<const float*>(qp_s);
        float s = 0.f;
        for (int lp = q8; lp < 64; lp += 8) s += Sff[l * 72 + lp];
        for (int j = 0; j < 16; j++) {
            int p = j * 8 + pq;
            s = fmaf(qpf[l * 136 + p], ks[p], s);
        }
        s += __shfl_xor_sync(0xffffffffu, s, 4);
        s += __shfl_xor_sync(0xffffffffu, s, 2);
        s += __shfl_xor_sync(0xffffffffu, s, 1);
        if (q8 == 0) den[l] = s;
    }
    __syncthreads();

    // ---- phase 4: num = S @ v (K=64) + qp @ KV (K=128); divide; store ----
    float nacc[2][4];
#pragma unroll
    for (int j = 0; j < 2; j++) nacc[j][0] = nacc[j][1] = nacc[j][2] = nacc[j][3] = 0.f;

    int sr0 = r0 * 72, sr1 = r1 * 72;
#pragma unroll
    for (int k0 = 0; k0 < 64; k0 += 8) {
        uint2 A0 = ld2(&Sfu[sr0 + k0 + 2 * t]);
        uint2 A1 = ld2(&Sfu[sr1 + k0 + 2 * t]);
#pragma unroll
        for (int j = 0; j < 2; j++) {
            int n = nt * 16 + j * 8 + g;
            uint2 Bn = ld2(&vT[n * 72 + k0 + 2 * t]);
            mma8(nacc[j], A0.x, A1.x, A0.y, A1.y, Bn.x, Bn.y);
        }
    }
#pragma unroll
    for (int k0 = 0; k0 < 128; k0 += 8) {
        uint2 A0 = ld2(&qp_s[qr0 + k0 + 2 * t]);
        uint2 A1 = ld2(&qp_s[qr1 + k0 + 2 * t]);
#pragma unroll
        for (int j = 0; j < 2; j++) {
            int n = nt * 16 + j * 8 + g;
            uint2 Bn = ld2(&kvT[n * 136 + k0 + 2 * t]);
            mma8(nacc[j], A0.x, A1.x, A0.y, A1.y, Bn.x, Bn.y);
        }
    }

    float i0 = 1.0f / den[r0];
    float i1 = 1.0f / den[r1];
    int ob = (b * Lq + lbase) * Hq + h;
#pragma unroll
    for (int j = 0; j < 2; j++) {
        int d = nt * 16 + j * 8 + 2 * t;
        float2 w0 = make_float2(nacc[j][0] * i0, nacc[j][1] * i0);
        float2 w1 = make_float2(nacc[j][2] * i1, nacc[j][3] * i1);
        reinterpret_cast<float2*>(OUT)[((ob + r0 * Hq) * Dq + d) >> 1] = w0;
        reinterpret_cast<float2*>(OUT)[((ob + r1 * Hq) * Dq + d) >> 1] = w1;
    }
}

// ============================ launch ============================
extern "C" void kernel_launch(void* const* d_in, const int* in_sizes, int n_in,
                              void* d_out, int out_size) {
    (void)in_sizes; (void)n_in; (void)out_size;
    const float* Q = (const float*)d_in[0];
    const float* K = (const float*)d_in[1];
    const float* V = (const float*)d_in[2];
    const float* P = (const float*)d_in[3];
    float* OUT = (float*)d_out;

    cudaFuncSetAttribute(chunkkv_kernel, cudaFuncAttributeMaxDynamicSharedMemorySize, CKV_SMEM);
    cudaFuncSetAttribute(out_kernel,     cudaFuncAttributeMaxDynamicSharedMemorySize, OUT_SMEM);

    chunkkv_kernel<<<BHq * NCq, 256, CKV_SMEM>>>(K, V, P);
    scan_kernel<<<BHq * 8, 256>>>();
    out_kernel<<<BHq * NCq, 512, OUT_SMEM>>>(Q, K, V, P, OUT);
}

// round 9
// speedup vs baseline: 2.1362x; 1.6504x over previous
#include <cuda_runtime.h>
#include <cuda_fp16.h>
#include <stdint.h>
#include <math.h>

// Problem constants (fixed by setup_inputs)
#define Bq 2
#define Lq 4096
#define Hq 8
#define Dq 64
#define Mq 128
#define Cq 64
#define NCq (Lq / Cq)      // 64 chunks
#define BHq (Bq * Hq)      // 16 sequences

#define RATIO 0.08838834764831845f   // 1/sqrt(128)
#define STAB  1e-3f

// ---------------- scratch (device globals; no runtime allocation) ----------
__device__ float g_kv[BHq * NCq * Mq * Dq];    // [bh, c, m, d] -> exclusive prefix
__device__ float g_ks[BHq * NCq * Mq];         // [bh, c, m]   -> exclusive prefix

// ---------------- helpers ----------------
__device__ __forceinline__ float4 f4z() { return make_float4(0.f, 0.f, 0.f, 0.f); }
__device__ __forceinline__ void add4(float4& a, float4 b) {
    a.x += b.x; a.y += b.y; a.z += b.z; a.w += b.w;
}
__device__ __forceinline__ uint32_t f2h2(float lo, float hi) {
    __half2 h = __floats2half2_rn(lo, hi);
    return *reinterpret_cast<uint32_t*>(&h);
}
__device__ __forceinline__ float relu_s(float x) { return fmaxf(x * RATIO, 0.f) + STAB; }

// m16n8k16 fp16 mma, fp32 accumulate (D = A*B + D)
// A row-major [16][16] halves: a0=[g][2t,2t+1], a1=[g+8][..], a2=[g][2t+8,..], a3=[g+8][2t+8..]
// B col-major [n=8][k=16]:     b0=[g][2t,2t+1], b1=[g][2t+8,2t+9]
// C: c0=[g][2t], c1=[g][2t+1], c2=[g+8][2t], c3=[g+8][2t+1]
__device__ __forceinline__ void mma16(float* c, uint32_t a0, uint32_t a1, uint32_t a2, uint32_t a3,
                                      uint32_t b0, uint32_t b1) {
    asm("mma.sync.aligned.m16n8k16.row.col.f32.f16.f16.f32 "
        "{%0,%1,%2,%3},{%4,%5,%6,%7},{%8,%9},{%0,%1,%2,%3};"
        : "+f"(c[0]), "+f"(c[1]), "+f"(c[2]), "+f"(c[3])
        : "r"(a0), "r"(a1), "r"(a2), "r"(a3), "r"(b0), "r"(b1));
}

// ======================= Kernel 1: chunk kp -> KV / ksum ====================
// grid BH*NC, 256 threads (8 warps), 54 KB smem.
// smem u32 (halves packed along k; stride 36 u32 == 4 mod 32 -> conflict-free):
//   Xk [64][36] (k=d) | Ps [128][36] (k=d) | kpT [128][36] ([m][l], k=l) | vT [64][36] ([d][l])
#define CKV_SMEM ((64 * 36 + 128 * 36 + 128 * 36 + 64 * 36) * 4)
__global__ void __launch_bounds__(256, 3) chunkkv_kernel(
        const float* __restrict__ K, const float* __restrict__ V,
        const float* __restrict__ P) {
    extern __shared__ uint32_t sm[];
    uint32_t* Xk  = sm;                 // [64][36]
    uint32_t* Ps  = Xk + 64 * 36;       // [128][36]
    uint32_t* kpT = Ps + 128 * 36;      // [128][36]
    uint32_t* vT  = kpT + 128 * 36;     // [64][36]
    __half*   kph = reinterpret_cast<__half*>(kpT);   // stride 72 halves
    __half*   vTh = reinterpret_cast<__half*>(vT);    // stride 72 halves

    int bid = blockIdx.x;
    int bh = bid / NCq, c = bid % NCq;
    int b = bh / Hq, h = bh % Hq;
    int tid = threadIdx.x;
    int lbase = c * Cq;

    for (int i = tid; i < 128 * 16; i += 256) {
        int m = i >> 4, d4 = i & 15;
        float4 v = reinterpret_cast<const float4*>(P)[m * 16 + d4];
        Ps[m * 36 + d4 * 2]     = f2h2(v.x, v.y);
        Ps[m * 36 + d4 * 2 + 1] = f2h2(v.z, v.w);
    }
    for (int i = tid; i < 64 * 16; i += 256) {
        int l = i >> 4, d4 = i & 15;
        int gidx = ((b * Lq + lbase + l) * Hq + h) * 16 + d4;
        float4 v = reinterpret_cast<const float4*>(K)[gidx];
        Xk[l * 36 + d4 * 2]     = f2h2(v.x, v.y);
        Xk[l * 36 + d4 * 2 + 1] = f2h2(v.z, v.w);
        float4 vv = reinterpret_cast<const float4*>(V)[gidx];
        vTh[(d4 * 4 + 0) * 72 + l] = __float2half_rn(vv.x);
        vTh[(d4 * 4 + 1) * 72 + l] = __float2half_rn(vv.y);
        vTh[(d4 * 4 + 2) * 72 + l] = __float2half_rn(vv.z);
        vTh[(d4 * 4 + 3) * 72 + l] = __float2half_rn(vv.w);
    }
    __syncthreads();

    int wid = tid >> 5, lane = tid & 31;
    int g = lane >> 2, t = lane & 3;

    // ---- kp = relu(Xk @ P^T) -> kpT [m][l] (8 warps: 4 l-tiles x 2 n-halves)
    {
        int mt = wid & 3, nh = wid >> 2;
        int l0 = mt * 16 + g, l1 = l0 + 8;
        int ar0 = l0 * 36, ar1 = l1 * 36;
        float acc[8][4];
#pragma unroll
        for (int j = 0; j < 8; j++) acc[j][0] = acc[j][1] = acc[j][2] = acc[j][3] = 0.f;
#pragma unroll
        for (int ks16 = 0; ks16 < 4; ks16++) {         // k over 64, step 16
            int kw = ks16 * 8;
            uint32_t a0 = Xk[ar0 + kw + t];
            uint32_t a1 = Xk[ar1 + kw + t];
            uint32_t a2 = Xk[ar0 + kw + t + 4];
            uint32_t a3 = Xk[ar1 + kw + t + 4];
#pragma unroll
            for (int j = 0; j < 8; j++) {
                int n = nh * 64 + j * 8 + g;
                mma16(acc[j], a0, a1, a2, a3, Ps[n * 36 + kw + t], Ps[n * 36 + kw + t + 4]);
            }
        }
#pragma unroll
        for (int j = 0; j < 8; j++) {
            int col = nh * 64 + j * 8 + 2 * t;
            kph[col * 72 + l0]       = __float2half_rn(relu_s(acc[j][0]));
            kph[(col + 1) * 72 + l0] = __float2half_rn(relu_s(acc[j][1]));
            kph[col * 72 + l1]       = __float2half_rn(relu_s(acc[j][2]));
            kph[(col + 1) * 72 + l1] = __float2half_rn(relu_s(acc[j][3]));
        }
    }
    __syncthreads();

    int cbase = (bh * NCq + c) * Mq;

    // ---- ksum[m] = sum_l kp[l][m] ----
    {
        int m = tid >> 1, half = tid & 1;
        float s = 0.f;
        for (int l = 0; l < 32; l++) s += __half2float(kph[m * 72 + half * 32 + l]);
        s += __shfl_xor_sync(0xffffffffu, s, 1);
        if (half == 0) g_ks[cbase + m] = s;
    }

    // ---- KV = kp^T @ v : A = kpT [m][l], B = vT [d][l], K=64 ----
    {
        int m0 = wid * 16 + g, m1 = m0 + 8;
        int ar0 = m0 * 36, ar1 = m1 * 36;
        float acc[8][4];
#pragma unroll
        for (int j = 0; j < 8; j++) acc[j][0] = acc[j][1] = acc[j][2] = acc[j][3] = 0.f;
#pragma unroll
        for (int ks16 = 0; ks16 < 4; ks16++) {
            int kw = ks16 * 8;
            uint32_t a0 = kpT[ar0 + kw + t];
            uint32_t a1 = kpT[ar1 + kw + t];
            uint32_t a2 = kpT[ar0 + kw + t + 4];
            uint32_t a3 = kpT[ar1 + kw + t + 4];
#pragma unroll
            for (int j = 0; j < 8; j++) {
                int n = j * 8 + g;
                mma16(acc[j], a0, a1, a2, a3, vT[n * 36 + kw + t], vT[n * 36 + kw + t + 4]);
            }
        }
#pragma unroll
        for (int j = 0; j < 8; j++) {
            int d = j * 8 + 2 * t;
            float2 w0 = make_float2(acc[j][0], acc[j][1]);
            float2 w1 = make_float2(acc[j][2], acc[j][3]);
            reinterpret_cast<float2*>(g_kv)[((cbase + m0) * Dq + d) >> 1] = w0;
            reinterpret_cast<float2*>(g_kv)[((cbase + m1) * Dq + d) >> 1] = w1;
        }
    }
}

// ======================= Kernel 2: exclusive prefix over chunks ==============
// grid BH*8 (8 slices per bh), 256 threads; each thread owns 1 float4; MLP=4
__global__ void scan_kernel() {
    int bh    = blockIdx.x >> 3;
    int slice = blockIdx.x & 7;
    int tid   = threadIdx.x;
    int base4 = slice * 256 + tid;          // per-(bh,c) = 2048 float4
    float4* kv4 = reinterpret_cast<float4*>(g_kv);

    float4 p = f4z();
    for (int c = 0; c < NCq; c += 4) {
        int i0 = (bh * NCq + c) * 2048 + base4;
        float4 a0 = kv4[i0];
        float4 a1 = kv4[i0 + 2048];
        float4 a2 = kv4[i0 + 4096];
        float4 a3 = kv4[i0 + 6144];
        kv4[i0]        = p; add4(p, a0);
        kv4[i0 + 2048] = p; add4(p, a1);
        kv4[i0 + 4096] = p; add4(p, a2);
        kv4[i0 + 6144] = p; add4(p, a3);
    }

    if (slice == 0 && tid < 128) {
        float pk = 0.f;
        for (int c = 0; c < NCq; c += 4) {
            int i0 = (bh * NCq + c) * Mq + tid;
            float a0 = g_ks[i0], a1 = g_ks[i0 + Mq], a2 = g_ks[i0 + 2 * Mq], a3 = g_ks[i0 + 3 * Mq];
            g_ks[i0]          = pk;
            g_ks[i0 + Mq]     = pk + a0;
            g_ks[i0 + 2 * Mq] = pk + a0 + a1;
            g_ks[i0 + 3 * Mq] = pk + a0 + a1 + a2;
            pk += a0 + a1 + a2 + a3;
        }
    }
}

// ======================= Kernel 3: fused proj + output ======================
// grid BH*NC, 512 threads (16 warps), ~80 KB smem -> 2 CTAs/SM.
// smem u32 (halves packed along k):
//   Xq [64][36] (-> Sf [64][36], k=l') | Xk [64][36] | Ps [128][36] (-> kvT [64][68], k=m)
//   qp_s [64][68] (k=m) | kp_s [64][68] (k=m) | vT [64][36] (k=l') | ks[128]f | den[64]f
#define OUT_SMEM ((2304 + 2304 + 4608 + 4352 + 4352 + 2304 + 192) * 4)
__global__ void __launch_bounds__(512, 2) out_kernel(
        const float* __restrict__ Q, const float* __restrict__ K,
        const float* __restrict__ V, const float* __restrict__ P,
        float* __restrict__ OUT) {
    extern __shared__ uint32_t sm[];
    uint32_t* Xq   = sm;               // [64][36] -> Sf after proj phase
    uint32_t* Xk   = Xq + 2304;        // [64][36]
    uint32_t* Ps   = Xk + 2304;        // [128][36] -> kvT [64][68] after proj
    uint32_t* qp_s = Ps + 4608;        // [64][68]
    uint32_t* kp_s = qp_s + 4352;      // [64][68]
    uint32_t* vT   = kp_s + 4352;      // [64][36]
    float*    ks   = reinterpret_cast<float*>(vT + 2304);  // [128]
    float*    den  = ks + 128;                              // [64]
    uint32_t* Sfu  = Xq;               // alias [64][36] ([l][l'/2])
    uint32_t* kvT  = Ps;               // alias [64][68] ([d][m/2])
    __half*   Sfh  = reinterpret_cast<__half*>(Sfu);   // stride 72
    __half*   vTh  = reinterpret_cast<__half*>(vT);    // stride 72
    __half*   kvh  = reinterpret_cast<__half*>(kvT);   // stride 136
    __half*   qph  = reinterpret_cast<__half*>(qp_s);  // stride 136

    int bid = blockIdx.x;
    int bh = bid / NCq, c = bid % NCq;
    int b = bh / Hq, h = bh % Hq;
    int tid = threadIdx.x;
    int lbase = c * Cq;

    // ---- phase 0: fills ----
    for (int i = tid; i < 128 * 16; i += 512) {
        int m = i >> 4, d4 = i & 15;
        float4 v = reinterpret_cast<const float4*>(P)[m * 16 + d4];
        Ps[m * 36 + d4 * 2]     = f2h2(v.x, v.y);
        Ps[m * 36 + d4 * 2 + 1] = f2h2(v.z, v.w);
    }
    for (int i = tid; i < 64 * 16; i += 512) {
        int l = i >> 4, d4 = i & 15;
        int gidx = ((b * Lq + lbase + l) * Hq + h) * 16 + d4;
        float4 q = reinterpret_cast<const float4*>(Q)[gidx];
        Xq[l * 36 + d4 * 2]     = f2h2(q.x, q.y);
        Xq[l * 36 + d4 * 2 + 1] = f2h2(q.z, q.w);
        float4 k = reinterpret_cast<const float4*>(K)[gidx];
        Xk[l * 36 + d4 * 2]     = f2h2(k.x, k.y);
        Xk[l * 36 + d4 * 2 + 1] = f2h2(k.z, k.w);
        float4 vv = reinterpret_cast<const float4*>(V)[gidx];
        vTh[(d4 * 4 + 0) * 72 + l] = __float2half_rn(vv.x);
        vTh[(d4 * 4 + 1) * 72 + l] = __float2half_rn(vv.y);
        vTh[(d4 * 4 + 2) * 72 + l] = __float2half_rn(vv.z);
        vTh[(d4 * 4 + 3) * 72 + l] = __float2half_rn(vv.w);
    }
    if (tid < 128) ks[tid] = g_ks[(bh * NCq + c) * Mq + tid];
    __syncthreads();

    int wid = tid >> 5, lane = tid & 31;
    int g = lane >> 2, t = lane & 3;

    // ---- phase 1: qp/kp = relu(X @ P^T); warps 0-7 qp, 8-15 kp ----
    {
        int pw = wid & 7, which = wid >> 3;
        uint32_t* src = which ? Xk : Xq;
        uint32_t* dst = which ? kp_s : qp_s;
        int mt = pw & 3, nh = pw >> 2;
        int r0 = mt * 16 + g, r1 = r0 + 8;
        int ar0 = r0 * 36, ar1 = r1 * 36;
        float acc[8][4];
#pragma unroll
        for (int j = 0; j < 8; j++) acc[j][0] = acc[j][1] = acc[j][2] = acc[j][3] = 0.f;
#pragma unroll
        for (int ks16 = 0; ks16 < 4; ks16++) {
            int kw = ks16 * 8;
            uint32_t a0 = src[ar0 + kw + t];
            uint32_t a1 = src[ar1 + kw + t];
            uint32_t a2 = src[ar0 + kw + t + 4];
            uint32_t a3 = src[ar1 + kw + t + 4];
#pragma unroll
            for (int j = 0; j < 8; j++) {
                int n = nh * 64 + j * 8 + g;
                mma16(acc[j], a0, a1, a2, a3, Ps[n * 36 + kw + t], Ps[n * 36 + kw + t + 4]);
            }
        }
#pragma unroll
        for (int j = 0; j < 8; j++) {
            int w = nh * 32 + j * 4 + t;     // (cols cb,cb+1)/2 with cb = nh*64+j*8+2t
            dst[r0 * 68 + w] = f2h2(relu_s(acc[j][0]), relu_s(acc[j][1]));
            dst[r1 * 68 + w] = f2h2(relu_s(acc[j][2]), relu_s(acc[j][3]));
        }
    }
    __syncthreads();

    int mt = wid & 3, nt = wid >> 2;
    int r0 = mt * 16 + g, r1 = r0 + 8;
    int qr0 = r0 * 68, qr1 = r1 * 68;

    // ---- phase 2: issue kv LDGs; S = qp @ kp^T (K=128); store Sf; scatter kvT
    float4 kvreg[4];
#pragma unroll
    for (int kk = 0; kk < 4; kk++) {
        int i = tid + kk * 512;                 // 2048 float4 = 128m x 16(d4)
        int m = i >> 4, d4 = i & 15;
        kvreg[kk] = reinterpret_cast<const float4*>(g_kv)[((bh * NCq + c) * Mq + m) * 16 + d4];
    }
    {
        float sacc[2][4];
#pragma unroll
        for (int j = 0; j < 2; j++) sacc[j][0] = sacc[j][1] = sacc[j][2] = sacc[j][3] = 0.f;
#pragma unroll
        for (int ks16 = 0; ks16 < 8; ks16++) {   // k over 128, step 16
            int kw = ks16 * 8;
            uint32_t a0 = qp_s[qr0 + kw + t];
            uint32_t a1 = qp_s[qr1 + kw + t];
            uint32_t a2 = qp_s[qr0 + kw + t + 4];
            uint32_t a3 = qp_s[qr1 + kw + t + 4];
#pragma unroll
            for (int j = 0; j < 2; j++) {
                int n = nt * 16 + j * 8 + g;
                mma16(sacc[j], a0, a1, a2, a3, kp_s[n * 68 + kw + t], kp_s[n * 68 + kw + t + 4]);
            }
        }
        // masked store into Sf (halves pair = cols cb, cb+1); Xq dead after phase 1
#pragma unroll
        for (int j = 0; j < 2; j++) {
            int cb = nt * 16 + j * 8 + 2 * t;
            int w = nt * 8 + j * 4 + t;          // cb/2
            Sfu[r0 * 36 + w] = f2h2((r0 >= cb) ? sacc[j][0] : 0.f,
                                    (r0 >= cb + 1) ? sacc[j][1] : 0.f);
            Sfu[r1 * 36 + w] = f2h2((r1 >= cb) ? sacc[j][2] : 0.f,
                                    (r1 >= cb + 1) ? sacc[j][3] : 0.f);
        }
    }
    // scatter kv into kvT [d][m] halves (Ps region; free after phase 1)
#pragma unroll
    for (int kk = 0; kk < 4; kk++) {
        int i = tid + kk * 512;
        int m = i >> 4, d4 = i & 15;
        kvh[(d4 * 4 + 0) * 136 + m] = __float2half_rn(kvreg[kk].x);
        kvh[(d4 * 4 + 1) * 136 + m] = __float2half_rn(kvreg[kk].y);
        kvh[(d4 * 4 + 2) * 136 + m] = __float2half_rn(kvreg[kk].z);
        kvh[(d4 * 4 + 3) * 136 + m] = __float2half_rn(kvreg[kk].w);
    }
    __syncthreads();

    // ---- phase 3: denominator (8 lanes per row) ----
    {
        int l = tid >> 3, q8 = tid & 7;
        float s = 0.f;
        for (int lp = q8; lp < 64; lp += 8) s += __half2float(Sfh[l * 72 + lp]);
        for (int m = q8; m < Mq; m += 8)   s = fmaf(__half2float(qph[l * 136 + m]), ks[m], s);
        s += __shfl_xor_sync(0xffffffffu, s, 4);
        s += __shfl_xor_sync(0xffffffffu, s, 2);
        s += __shfl_xor_sync(0xffffffffu, s, 1);
        if (q8 == 0) den[l] = s;
    }
    __syncthreads();

    // ---- phase 4: num = S @ v (K=64) + qp @ KV (K=128); divide; store ----
    float nacc[2][4];
#pragma unroll
    for (int j = 0; j < 2; j++) nacc[j][0] = nacc[j][1] = nacc[j][2] = nacc[j][3] = 0.f;

    int sr0 = r0 * 36, sr1 = r1 * 36;
#pragma unroll
    for (int ks16 = 0; ks16 < 4; ks16++) {
        int kw = ks16 * 8;
        uint32_t a0 = Sfu[sr0 + kw + t];
        uint32_t a1 = Sfu[sr1 + kw + t];
        uint32_t a2 = Sfu[sr0 + kw + t + 4];
        uint32_t a3 = Sfu[sr1 + kw + t + 4];
#pragma unroll
        for (int j = 0; j < 2; j++) {
            int n = nt * 16 + j * 8 + g;
            mma16(nacc[j], a0, a1, a2, a3, vT[n * 36 + kw + t], vT[n * 36 + kw + t + 4]);
        }
    }
#pragma unroll
    for (int ks16 = 0; ks16 < 8; ks16++) {
        int kw = ks16 * 8;
        uint32_t a0 = qp_s[qr0 + kw + t];
        uint32_t a1 = qp_s[qr1 + kw + t];
        uint32_t a2 = qp_s[qr0 + kw + t + 4];
        uint32_t a3 = qp_s[qr1 + kw + t + 4];
#pragma unroll
        for (int j = 0; j < 2; j++) {
            int n = nt * 16 + j * 8 + g;
            mma16(nacc[j], a0, a1, a2, a3, kvT[n * 68 + kw + t], kvT[n * 68 + kw + t + 4]);
        }
    }

    float i0 = 1.0f / den[r0];
    float i1 = 1.0f / den[r1];
    int ob = (b * Lq + lbase) * Hq + h;
#pragma unroll
    for (int j = 0; j < 2; j++) {
        int d = nt * 16 + j * 8 + 2 * t;
        float2 w0 = make_float2(nacc[j][0] * i0, nacc[j][1] * i0);
        float2 w1 = make_float2(nacc[j][2] * i1, nacc[j][3] * i1);
        reinterpret_cast<float2*>(OUT)[((ob + r0 * Hq) * Dq + d) >> 1] = w0;
        reinterpret_cast<float2*>(OUT)[((ob + r1 * Hq) * Dq + d) >> 1] = w1;
    }
}

// ============================ launch ============================
extern "C" void kernel_launch(void* const* d_in, const int* in_sizes, int n_in,
                              void* d_out, int out_size) {
    (void)in_sizes; (void)n_in; (void)out_size;
    const float* Q = (const float*)d_in[0];
    const float* K = (const float*)d_in[1];
    const float* V = (const float*)d_in[2];
    const float* P = (const float*)d_in[3];
    float* OUT = (float*)d_out;

    cudaFuncSetAttribute(chunkkv_kernel, cudaFuncAttributeMaxDynamicSharedMemorySize, CKV_SMEM);
    cudaFuncSetAttribute(out_kernel,     cudaFuncAttributeMaxDynamicSharedMemorySize, OUT_SMEM);

    chunkkv_kernel<<<BHq * NCq, 256, CKV_SMEM>>>(K, V, P);
    scan_kernel<<<BHq * 8, 256>>>();
    out_kernel<<<BHq * NCq, 512, OUT_SMEM>>>(Q, K, V, P, OUT);
}

// round 13
// speedup vs baseline: 2.5435x; 1.1906x over previous
#include <cuda_runtime.h>
#include <cuda_fp16.h>
#include <stdint.h>
#include <math.h>

// Problem constants (fixed by setup_inputs)
#define Bq 2
#define Lq 4096
#define Hq 8
#define Dq 64
#define Mq 128
#define Cq 64
#define NCq (Lq / Cq)      // 64 chunks
#define BHq (Bq * Hq)      // 16 sequences

#define RATIO 0.08838834764831845f   // 1/sqrt(128)
#define STAB  1e-3f

// ---------------- scratch (device globals; no runtime allocation) ----------
__device__ __half g_kvh[BHq * NCq * Dq * Mq];  // [bh, c, d, m] -> exclusive prefix (fp16)
__device__ float  g_ks[BHq * NCq * Mq];        // [bh, c, m]    -> exclusive prefix

// ---------------- helpers ----------------
__device__ __forceinline__ uint32_t f2h2(float lo, float hi) {
    __half2 h = __floats2half2_rn(lo, hi);
    return *reinterpret_cast<uint32_t*>(&h);
}
__device__ __forceinline__ void acc2(float* p, uint32_t u) {
    __half2 h = *reinterpret_cast<__half2*>(&u);
    float2 f = __half22float2(h);
    p[0] += f.x; p[1] += f.y;
}
__device__ __forceinline__ float relu_s(float x) { return fmaxf(x * RATIO, 0.f) + STAB; }

// m16n8k16 fp16 mma, fp32 accumulate (D = A*B + D)
__device__ __forceinline__ void mma16(float* c, uint32_t a0, uint32_t a1, uint32_t a2, uint32_t a3,
                                      uint32_t b0, uint32_t b1) {
    asm("mma.sync.aligned.m16n8k16.row.col.f32.f16.f16.f32 "
        "{%0,%1,%2,%3},{%4,%5,%6,%7},{%8,%9},{%0,%1,%2,%3};"
        : "+f"(c[0]), "+f"(c[1]), "+f"(c[2]), "+f"(c[3])
        : "r"(a0), "r"(a1), "r"(a2), "r"(a3), "r"(b0), "r"(b1));
}

// ======================= Kernel 1: chunk kp -> KV^T / ksum ==================
// grid BH*NC, 256 threads (8 warps), 54 KB smem, 3 CTAs/SM.
// smem u32: Xk [64][36] | Ps [128][36] | kpT [128][36] ([m][l]) | vT [64][36] ([d][l])
// stage (KV^T [64 d][128 m] halves as [64][68] u32) aliases Xk+Ps after proj.
#define CKV_SMEM ((2304 + 4608 + 4608 + 2304) * 4)
__global__ void __launch_bounds__(256, 3) chunkkv_kernel(
        const float* __restrict__ K, const float* __restrict__ V,
        const float* __restrict__ P) {
    extern __shared__ uint32_t sm[];
    uint32_t* Xk    = sm;               // [64][36]
    uint32_t* Ps    = Xk + 2304;        // [128][36]
    uint32_t* kpT   = Ps + 4608;        // [128][36]
    uint32_t* vT    = kpT + 4608;       // [64][36]
    uint32_t* stage = sm;               // alias [64][68] (free after proj)
    __half*   kph = reinterpret_cast<__half*>(kpT);   // stride 72 halves
    __half*   vTh = reinterpret_cast<__half*>(vT);    // stride 72 halves

    int bid = blockIdx.x;
    int bh = bid / NCq, c = bid % NCq;
    int b = bh / Hq, h = bh % Hq;
    int tid = threadIdx.x;
    int lbase = c * Cq;

    for (int i = tid; i < 128 * 16; i += 256) {
        int m = i >> 4, d4 = i & 15;
        float4 v = reinterpret_cast<const float4*>(P)[m * 16 + d4];
        Ps[m * 36 + d4 * 2]     = f2h2(v.x, v.y);
        Ps[m * 36 + d4 * 2 + 1] = f2h2(v.z, v.w);
    }
    for (int i = tid; i < 64 * 16; i += 256) {
        int l = i >> 4, d4 = i & 15;
        int gidx = ((b * Lq + lbase + l) * Hq + h) * 16 + d4;
        float4 v = reinterpret_cast<const float4*>(K)[gidx];
        Xk[l * 36 + d4 * 2]     = f2h2(v.x, v.y);
        Xk[l * 36 + d4 * 2 + 1] = f2h2(v.z, v.w);
        float4 vv = reinterpret_cast<const float4*>(V)[gidx];
        vTh[(d4 * 4 + 0) * 72 + l] = __float2half_rn(vv.x);
        vTh[(d4 * 4 + 1) * 72 + l] = __float2half_rn(vv.y);
        vTh[(d4 * 4 + 2) * 72 + l] = __float2half_rn(vv.z);
        vTh[(d4 * 4 + 3) * 72 + l] = __float2half_rn(vv.w);
    }
    __syncthreads();

    int wid = tid >> 5, lane = tid & 31;
    int g = lane >> 2, t = lane & 3;

    // ---- kp = relu(Xk @ P^T) -> kpT [m][l]; 8 warps, 32x32 tiles ----
    {
        int lt = wid & 1, nq = wid >> 1;       // 2 row-tiles x 4 col-tiles
        int r0 = lt * 32 + g;
        float acc[2][4][4];
#pragma unroll
        for (int rb = 0; rb < 2; rb++)
#pragma unroll
            for (int j = 0; j < 4; j++)
                acc[rb][j][0] = acc[rb][j][1] = acc[rb][j][2] = acc[rb][j][3] = 0.f;
#pragma unroll
        for (int ks16 = 0; ks16 < 4; ks16++) {
            int kw = ks16 * 8;
            uint32_t a[2][4];
            a[0][0] = Xk[(r0)      * 36 + kw + t];
            a[0][1] = Xk[(r0 + 8)  * 36 + kw + t];
            a[0][2] = Xk[(r0)      * 36 + kw + t + 4];
            a[0][3] = Xk[(r0 + 8)  * 36 + kw + t + 4];
            a[1][0] = Xk[(r0 + 16) * 36 + kw + t];
            a[1][1] = Xk[(r0 + 24) * 36 + kw + t];
            a[1][2] = Xk[(r0 + 16) * 36 + kw + t + 4];
            a[1][3] = Xk[(r0 + 24) * 36 + kw + t + 4];
#pragma unroll
            for (int j = 0; j < 4; j++) {
                int n = nq * 32 + j * 8 + g;
                uint32_t b0 = Ps[n * 36 + kw + t], b1 = Ps[n * 36 + kw + t + 4];
                mma16(acc[0][j], a[0][0], a[0][1], a[0][2], a[0][3], b0, b1);
                mma16(acc[1][j], a[1][0], a[1][1], a[1][2], a[1][3], b0, b1);
            }
        }
#pragma unroll
        for (int rb = 0; rb < 2; rb++)
#pragma unroll
            for (int j = 0; j < 4; j++) {
                int row0 = lt * 32 + rb * 16 + g, row1 = row0 + 8;
                int col = nq * 32 + j * 8 + 2 * t;
                kph[col * 72 + row0]       = __float2half_rn(relu_s(acc[rb][j][0]));
                kph[(col + 1) * 72 + row0] = __float2half_rn(relu_s(acc[rb][j][1]));
                kph[col * 72 + row1]       = __float2half_rn(relu_s(acc[rb][j][2]));
                kph[(col + 1) * 72 + row1] = __float2half_rn(relu_s(acc[rb][j][3]));
            }
    }
    __syncthreads();

    int cbase = bh * NCq + c;

    // ---- ksum[m] = sum_l kp[l][m] ----
    {
        int m = tid >> 1, half = tid & 1;
        float s = 0.f;
        for (int l = 0; l < 32; l++) s += __half2float(kph[m * 72 + half * 32 + l]);
        s += __shfl_xor_sync(0xffffffffu, s, 1);
        if (half == 0) g_ks[cbase * Mq + m] = s;
    }

    // ---- KV^T = v^T @ kp : A = vT [d][l], B = kpT [m][l]; 32x32 tiles ----
    {
        int dt = wid & 1, mq = wid >> 1;
        int d0 = dt * 32 + g;
        float acc[2][4][4];
#pragma unroll
        for (int rb = 0; rb < 2; rb++)
#pragma unroll
            for (int j = 0; j < 4; j++)
                acc[rb][j][0] = acc[rb][j][1] = acc[rb][j][2] = acc[rb][j][3] = 0.f;
#pragma unroll
        for (int ks16 = 0; ks16 < 4; ks16++) {
            int kw = ks16 * 8;
            uint32_t a[2][4];
            a[0][0] = vT[(d0)      * 36 + kw + t];
            a[0][1] = vT[(d0 + 8)  * 36 + kw + t];
            a[0][2] = vT[(d0)      * 36 + kw + t + 4];
            a[0][3] = vT[(d0 + 8)  * 36 + kw + t + 4];
            a[1][0] = vT[(d0 + 16) * 36 + kw + t];
            a[1][1] = vT[(d0 + 24) * 36 + kw + t];
            a[1][2] = vT[(d0 + 16) * 36 + kw + t + 4];
            a[1][3] = vT[(d0 + 24) * 36 + kw + t + 4];
#pragma unroll
            for (int j = 0; j < 4; j++) {
                int n = mq * 32 + j * 8 + g;
                uint32_t b0 = kpT[n * 36 + kw + t], b1 = kpT[n * 36 + kw + t + 4];
                mma16(acc[0][j], a[0][0], a[0][1], a[0][2], a[0][3], b0, b1);
                mma16(acc[1][j], a[1][0], a[1][1], a[1][2], a[1][3], b0, b1);
            }
        }
        // stage KV^T halves [d][m/2] (Xk+Ps region; all proj reads done)
#pragma unroll
        for (int rb = 0; rb < 2; rb++)
#pragma unroll
            for (int j = 0; j < 4; j++) {
                int row0 = dt * 32 + rb * 16 + g;
                int w = mq * 16 + j * 4 + t;
                stage[row0 * 68 + w]       = f2h2(acc[rb][j][0], acc[rb][j][1]);
                stage[(row0 + 8) * 68 + w] = f2h2(acc[rb][j][2], acc[rb][j][3]);
            }
    }
    __syncthreads();

    // ---- coalesced store: 64 rows x 16 uint4 ----
    uint4* dst4 = reinterpret_cast<uint4*>(g_kvh) + cbase * 1024;
#pragma unroll
    for (int it = 0; it < 4; it++) {
        int i = tid + it * 256;
        int row = i >> 4, q = i & 15;
        dst4[row * 16 + q] = *reinterpret_cast<uint4*>(&stage[row * 68 + q * 4]);
    }
}

// ======================= Kernel 2: exclusive prefix over chunks ==============
// grid BH*4, 256 threads; each thread owns 8 halves (1 uint4); fp32 accum; MLP=4
__global__ void scan_kernel() {
    int bh    = blockIdx.x >> 2;
    int slice = blockIdx.x & 3;
    int tid   = threadIdx.x;
    int base  = slice * 256 + tid;          // uint4 index within chunk (1024/chunk)
    uint4* kv4 = reinterpret_cast<uint4*>(g_kvh);

    float p[8];
#pragma unroll
    for (int j = 0; j < 8; j++) p[j] = 0.f;

    for (int c = 0; c < NCq; c += 4) {
        int i0 = (bh * NCq + c) * 1024 + base;
        uint4 a0 = kv4[i0];
        uint4 a1 = kv4[i0 + 1024];
        uint4 a2 = kv4[i0 + 2048];
        uint4 a3 = kv4[i0 + 3072];
#pragma unroll
        for (int u = 0; u < 4; u++) {
            uint4 a = (u == 0) ? a0 : (u == 1) ? a1 : (u == 2) ? a2 : a3;
            uint4 w;
            w.x = f2h2(p[0], p[1]); w.y = f2h2(p[2], p[3]);
            w.z = f2h2(p[4], p[5]); w.w = f2h2(p[6], p[7]);
            kv4[i0 + u * 1024] = w;
            acc2(p + 0, a.x); acc2(p + 2, a.y);
            acc2(p + 4, a.z); acc2(p + 6, a.w);
        }
    }

    if (slice == 0 && tid < 128) {
        float pk = 0.f;
        for (int c = 0; c < NCq; c += 4) {
            int i0 = (bh * NCq + c) * Mq + tid;
            float a0 = g_ks[i0], a1 = g_ks[i0 + Mq], a2 = g_ks[i0 + 2 * Mq], a3 = g_ks[i0 + 3 * Mq];
            g_ks[i0]          = pk;
            g_ks[i0 + Mq]     = pk + a0;
            g_ks[i0 + 2 * Mq] = pk + a0 + a1;
            g_ks[i0 + 3 * Mq] = pk + a0 + a1 + a2;
            pk += a0 + a1 + a2 + a3;
        }
    }
}

// ======================= Kernel 3: fused proj + output ======================
// grid BH*NC, 512 threads (16 warps), ~80 KB smem, 2 CTAs/SM.
// smem u32:
//   Xq [64][36] (-> Sf) | Xk [64][36] | Ps [128][36] (-> kvT [64][68])
//   qp_s [64][68] | kp_s [64][68] | vT [64][36] | ks[128]f | den[64]f
#define OUT_SMEM ((2304 + 2304 + 4608 + 4352 + 4352 + 2304 + 192) * 4)
__global__ void __launch_bounds__(512, 2) out_kernel(
        const float* __restrict__ Q, const float* __restrict__ K,
        const float* __restrict__ V, const float* __restrict__ P,
        float* __restrict__ OUT) {
    extern __shared__ uint32_t sm[];
    uint32_t* Xq   = sm;               // [64][36] -> Sf after proj phase
    uint32_t* Xk   = Xq + 2304;        // [64][36]
    uint32_t* Ps   = Xk + 2304;        // [128][36] -> kvT [64][68] after proj
    uint32_t* qp_s = Ps + 4608;        // [64][68]
    uint32_t* kp_s = qp_s + 4352;      // [64][68]
    uint32_t* vT   = kp_s + 4352;      // [64][36]
    float*    ks   = reinterpret_cast<float*>(vT + 2304);  // [128]
    float*    den  = ks + 128;                              // [64]
    uint32_t* Sfu  = Xq;               // alias [64][36] ([l][l'/2])
    uint32_t* kvT  = Ps;               // alias [64][68] ([d][m/2])
    __half*   Sfh  = reinterpret_cast<__half*>(Sfu);   // stride 72
    __half*   vTh  = reinterpret_cast<__half*>(vT);    // stride 72
    __half*   qph  = reinterpret_cast<__half*>(qp_s);  // stride 136

    int bid = blockIdx.x;
    int bh = bid / NCq, c = bid % NCq;
    int b = bh / Hq, h = bh % Hq;
    int tid = threadIdx.x;
    int lbase = c * Cq;

    // ---- phase 0: fills ----
    for (int i = tid; i < 128 * 16; i += 512) {
        int m = i >> 4, d4 = i & 15;
        float4 v = reinterpret_cast<const float4*>(P)[m * 16 + d4];
        Ps[m * 36 + d4 * 2]     = f2h2(v.x, v.y);
        Ps[m * 36 + d4 * 2 + 1] = f2h2(v.z, v.w);
    }
    for (int i = tid; i < 64 * 16; i += 512) {
        int l = i >> 4, d4 = i & 15;
        int gidx = ((b * Lq + lbase + l) * Hq + h) * 16 + d4;
        float4 q = reinterpret_cast<const float4*>(Q)[gidx];
        Xq[l * 36 + d4 * 2]     = f2h2(q.x, q.y);
        Xq[l * 36 + d4 * 2 + 1] = f2h2(q.z, q.w);
        float4 k = reinterpret_cast<const float4*>(K)[gidx];
        Xk[l * 36 + d4 * 2]     = f2h2(k.x, k.y);
        Xk[l * 36 + d4 * 2 + 1] = f2h2(k.z, k.w);
        float4 vv = reinterpret_cast<const float4*>(V)[gidx];
        vTh[(d4 * 4 + 0) * 72 + l] = __float2half_rn(vv.x);
        vTh[(d4 * 4 + 1) * 72 + l] = __float2half_rn(vv.y);
        vTh[(d4 * 4 + 2) * 72 + l] = __float2half_rn(vv.z);
        vTh[(d4 * 4 + 3) * 72 + l] = __float2half_rn(vv.w);
    }
    if (tid < 128) ks[tid] = g_ks[(bh * NCq + c) * Mq + tid];
    __syncthreads();

    int wid = tid >> 5, lane = tid & 31;
    int g = lane >> 2, t = lane & 3;

    // ---- phase 1: qp/kp = relu(X @ P^T); warps 0-7 qp, 8-15 kp; 32x32 tiles
    {
        int pw = wid & 7, which = wid >> 3;
        uint32_t* src = which ? Xk : Xq;
        uint32_t* dst = which ? kp_s : qp_s;
        int lt = pw & 1, nq = pw >> 1;
        int r0 = lt * 32 + g;
        float acc[2][4][4];
#pragma unroll
        for (int rb = 0; rb < 2; rb++)
#pragma unroll
            for (int j = 0; j < 4; j++)
                acc[rb][j][0] = acc[rb][j][1] = acc[rb][j][2] = acc[rb][j][3] = 0.f;
#pragma unroll
        for (int ks16 = 0; ks16 < 4; ks16++) {
            int kw = ks16 * 8;
            uint32_t a[2][4];
            a[0][0] = src[(r0)      * 36 + kw + t];
            a[0][1] = src[(r0 + 8)  * 36 + kw + t];
            a[0][2] = src[(r0)      * 36 + kw + t + 4];
            a[0][3] = src[(r0 + 8)  * 36 + kw + t + 4];
            a[1][0] = src[(r0 + 16) * 36 + kw + t];
            a[1][1] = src[(r0 + 24) * 36 + kw + t];
            a[1][2] = src[(r0 + 16) * 36 + kw + t + 4];
            a[1][3] = src[(r0 + 24) * 36 + kw + t + 4];
#pragma unroll
            for (int j = 0; j < 4; j++) {
                int n = nq * 32 + j * 8 + g;
                uint32_t b0 = Ps[n * 36 + kw + t], b1 = Ps[n * 36 + kw + t + 4];
                mma16(acc[0][j], a[0][0], a[0][1], a[0][2], a[0][3], b0, b1);
                mma16(acc[1][j], a[1][0], a[1][1], a[1][2], a[1][3], b0, b1);
            }
        }
#pragma unroll
        for (int rb = 0; rb < 2; rb++)
#pragma unroll
            for (int j = 0; j < 4; j++) {
                int row0 = lt * 32 + rb * 16 + g;
                int w = nq * 16 + j * 4 + t;
                dst[row0 * 68 + w]       = f2h2(relu_s(acc[rb][j][0]), relu_s(acc[rb][j][1]));
                dst[(row0 + 8) * 68 + w] = f2h2(relu_s(acc[rb][j][2]), relu_s(acc[rb][j][3]));
            }
    }
    __syncthreads();

    int mt = wid & 3, nt = wid >> 2;
    int r0 = mt * 16 + g, r1 = r0 + 8;
    int qr0 = r0 * 68, qr1 = r1 * 68;

    // ---- phase 2: kv LDG (hidden under S); S = qp @ kp^T; STS kvT; Sf ----
    uint4 kvr0, kvr1;
    {
        const uint4* src4 = reinterpret_cast<const uint4*>(g_kvh) + (bh * NCq + c) * 1024;
        kvr0 = src4[tid];
        kvr1 = src4[tid + 512];
    }
    {
        float sacc[2][4];
#pragma unroll
        for (int j = 0; j < 2; j++) sacc[j][0] = sacc[j][1] = sacc[j][2] = sacc[j][3] = 0.f;
#pragma unroll
        for (int ks16 = 0; ks16 < 8; ks16++) {   // k over 128, step 16
            int kw = ks16 * 8;
            uint32_t a0 = qp_s[qr0 + kw + t];
            uint32_t a1 = qp_s[qr1 + kw + t];
            uint32_t a2 = qp_s[qr0 + kw + t + 4];
            uint32_t a3 = qp_s[qr1 + kw + t + 4];
#pragma unroll
            for (int j = 0; j < 2; j++) {
                int n = nt * 16 + j * 8 + g;
                mma16(sacc[j], a0, a1, a2, a3, kp_s[n * 68 + kw + t], kp_s[n * 68 + kw + t + 4]);
            }
        }
        // STS kv into kvT (Ps region; phase-1 reads done)
        {
            int row = tid >> 4, q = tid & 15;
            *reinterpret_cast<uint4*>(&kvT[row * 68 + q * 4]) = kvr0;
            int i2 = tid + 512;
            int row2 = i2 >> 4, q2 = i2 & 15;
            *reinterpret_cast<uint4*>(&kvT[row2 * 68 + q2 * 4]) = kvr1;
        }
        // masked store into Sf (Xq region; dead after phase 1)
#pragma unroll
        for (int j = 0; j < 2; j++) {
            int cb = nt * 16 + j * 8 + 2 * t;
            int w = nt * 8 + j * 4 + t;
            Sfu[r0 * 36 + w] = f2h2((r0 >= cb) ? sacc[j][0] : 0.f,
                                    (r0 >= cb + 1) ? sacc[j][1] : 0.f);
            Sfu[r1 * 36 + w] = f2h2((r1 >= cb) ? sacc[j][2] : 0.f,
                                    (r1 >= cb + 1) ? sacc[j][3] : 0.f);
        }
    }
    __syncthreads();

    // ---- phase 3: denominator (8 lanes per row) ----
    {
        int l = tid >> 3, q8 = tid & 7;
        float s = 0.f;
        for (int lp = q8; lp < 64; lp += 8) s += __half2float(Sfh[l * 72 + lp]);
        for (int m = q8; m < Mq; m += 8)   s = fmaf(__half2float(qph[l * 136 + m]), ks[m], s);
        s += __shfl_xor_sync(0xffffffffu, s, 4);
        s += __shfl_xor_sync(0xffffffffu, s, 2);
        s += __shfl_xor_sync(0xffffffffu, s, 1);
        if (q8 == 0) den[l] = s;
    }
    __syncthreads();

    // ---- phase 4: num = S @ v (K=64) + qp @ KV (K=128); divide; store ----
    float nacc[2][4];
#pragma unroll
    for (int j = 0; j < 2; j++) nacc[j][0] = nacc[j][1] = nacc[j][2] = nacc[j][3] = 0.f;

    int sr0 = r0 * 36, sr1 = r1 * 36;
#pragma unroll
    for (int ks16 = 0; ks16 < 4; ks16++) {
        int kw = ks16 * 8;
        uint32_t a0 = Sfu[sr0 + kw + t];
        uint32_t a1 = Sfu[sr1 + kw + t];
        uint32_t a2 = Sfu[sr0 + kw + t + 4];
        uint32_t a3 = Sfu[sr1 + kw + t + 4];
#pragma unroll
        for (int j = 0; j < 2; j++) {
            int n = nt * 16 + j * 8 + g;
            mma16(nacc[j], a0, a1, a2, a3, vT[n * 36 + kw + t], vT[n * 36 + kw + t + 4]);
        }
    }
#pragma unroll
    for (int ks16 = 0; ks16 < 8; ks16++) {
        int kw = ks16 * 8;
        uint32_t a0 = qp_s[qr0 + kw + t];
        uint32_t a1 = qp_s[qr1 + kw + t];
        uint32_t a2 = qp_s[qr0 + kw + t + 4];
        uint32_t a3 = qp_s[qr1 + kw + t + 4];
#pragma unroll
        for (int j = 0; j < 2; j++) {
            int n = nt * 16 + j * 8 + g;
            mma16(nacc[j], a0, a1, a2, a3, kvT[n * 68 + kw + t], kvT[n * 68 + kw + t + 4]);
        }
    }

    float i0 = 1.0f / den[r0];
    float i1 = 1.0f / den[r1];
    int ob = (b * Lq + lbase) * Hq + h;
#pragma unroll
    for (int j = 0; j < 2; j++) {
        int d = nt * 16 + j * 8 + 2 * t;
        float2 w0 = make_float2(nacc[j][0] * i0, nacc[j][1] * i0);
        float2 w1 = make_float2(nacc[j][2] * i1, nacc[j][3] * i1);
        reinterpret_cast<float2*>(OUT)[((ob + r0 * Hq) * Dq + d) >> 1] = w0;
        reinterpret_cast<float2*>(OUT)[((ob + r1 * Hq) * Dq + d) >> 1] = w1;
    }
}

// ============================ launch ============================
extern "C" void kernel_launch(void* const* d_in, const int* in_sizes, int n_in,
                              void* d_out, int out_size) {
    (void)in_sizes; (void)n_in; (void)out_size;
    const float* Q = (const float*)d_in[0];
    const float* K = (const float*)d_in[1];
    const float* V = (const float*)d_in[2];
    const float* P = (const float*)d_in[3];
    float* OUT = (float*)d_out;

    cudaFuncSetAttribute(chunkkv_kernel, cudaFuncAttributeMaxDynamicSharedMemorySize, CKV_SMEM);
    cudaFuncSetAttribute(out_kernel,     cudaFuncAttributeMaxDynamicSharedMemorySize, OUT_SMEM);

    chunkkv_kernel<<<BHq * NCq, 256, CKV_SMEM>>>(K, V, P);
    scan_kernel<<<BHq * 4, 256>>>();
    out_kernel<<<BHq * NCq, 512, OUT_SMEM>>>(Q, K, V, P, OUT);
}